// round 9
// baseline (speedup 1.0000x reference)
#include <cuda_runtime.h>
#include <cuda_fp16.h>
#include <cstdint>

// Problem dims
#define BATCH 8
#define SEQ   2048
#define KDIM  4096
#define MDIM  4096
#define NDIM  (BATCH * SEQ)   // 16384

// GEMM tiling: CTA 128x256x64, 8 warps (2m x 4n), warp tile 64x64
#define BM 128
#define BN 256
#define BK 64
#define NST 4
#define GTHREADS 256
#define KITERS (KDIM / BK)    // 64

#define A_BYTES (BM * 128)                 // 16384
#define B_BYTES (BN * 128)                 // 32768
#define STAGE_BYTES (A_BYTES + B_BYTES)    // 49152
#define SMEM_TOTAL (NST * STAGE_BYTES)     // 196608

// fp16 scratch
__device__ __align__(16) __half g_Wh[(size_t)MDIM * KDIM];   // 32 MB
__device__ __align__(16) __half g_Xh[(size_t)NDIM * KDIM];   // 128 MB

// ---------------------------------------------------------------------------
// Conversion kernels
// ---------------------------------------------------------------------------
__global__ void convert_w_kernel(const float* __restrict__ w,
                                 const int* __restrict__ mask) {
    size_t total4 = (size_t)MDIM * KDIM / 4;
    for (size_t i = (size_t)blockIdx.x * blockDim.x + threadIdx.x;
         i < total4; i += (size_t)gridDim.x * blockDim.x) {
        float4 wv = reinterpret_cast<const float4*>(w)[i];
        int4   mv = reinterpret_cast<const int4*>(mask)[i];
        float a = mv.x ? wv.x : 0.0f;
        float b = mv.y ? wv.y : 0.0f;
        float c = mv.z ? wv.z : 0.0f;
        float d = mv.w ? wv.w : 0.0f;
        __half2* o = reinterpret_cast<__half2*>(&g_Wh[i * 4]);
        o[0] = __floats2half2_rn(a, b);
        o[1] = __floats2half2_rn(c, d);
    }
}

__global__ void convert_x_kernel(const float* __restrict__ x) {
    size_t total4 = (size_t)NDIM * KDIM / 4;
    for (size_t i = (size_t)blockIdx.x * blockDim.x + threadIdx.x;
         i < total4; i += (size_t)gridDim.x * blockDim.x) {
        float4 xv = reinterpret_cast<const float4*>(x)[i];
        __half2* o = reinterpret_cast<__half2*>(&g_Xh[i * 4]);
        o[0] = __floats2half2_rn(xv.x, xv.y);
        o[1] = __floats2half2_rn(xv.z, xv.w);
    }
}

// ---------------------------------------------------------------------------
// Helpers
// ---------------------------------------------------------------------------
__device__ __forceinline__ uint32_t smem_u32(const void* p) {
    uint32_t a;
    asm("{ .reg .u64 t; cvta.to.shared.u64 t, %1; cvt.u32.u64 %0, t; }"
        : "=r"(a) : "l"(p));
    return a;
}

__device__ __forceinline__ void ldsm_x4(uint32_t& r0, uint32_t& r1,
                                        uint32_t& r2, uint32_t& r3,
                                        uint32_t addr) {
    asm volatile("ldmatrix.sync.aligned.m8n8.x4.shared.b16 {%0,%1,%2,%3}, [%4];"
                 : "=r"(r0), "=r"(r1), "=r"(r2), "=r"(r3) : "r"(addr));
}

// f16-accumulate mma: D,C are 2x f16x2 regs
__device__ __forceinline__ void mma16816h(uint32_t& d0, uint32_t& d1,
                                          const uint32_t* a,
                                          uint32_t b0, uint32_t b1) {
    asm volatile(
        "mma.sync.aligned.m16n8k16.row.col.f16.f16.f16.f16 "
        "{%0,%1}, {%2,%3,%4,%5}, {%6,%7}, {%0,%1};"
        : "+r"(d0), "+r"(d1)
        : "r"(a[0]), "r"(a[1]), "r"(a[2]), "r"(a[3]), "r"(b0), "r"(b1));
}

// ---------------------------------------------------------------------------
// Producer: 3072 x 16B cp.async per stage (A 1024, B 2048), 12 per thread.
// ---------------------------------------------------------------------------
__device__ __forceinline__ void produce(uint32_t stage, int tid, int j,
                                        int mBase, int nBase) {
    const __half* aseg = &g_Wh[(size_t)mBase * KDIM + j * BK];
    const __half* bseg = &g_Xh[(size_t)nBase * KDIM + j * BK];
#pragma unroll
    for (int t = 0; t < 12; t++) {
        int id = tid + t * GTHREADS;          // 0..3071
        int isB = (id >= 1024);
        int lid = isB ? (id - 1024) : id;
        int row = lid >> 3;
        int c   = lid & 7;
        const __half* src = (isB ? bseg : aseg) + (size_t)row * KDIM + c * 8;
        uint32_t off = row * 128 + c * 16;
        uint32_t dst = stage + (isB ? A_BYTES : 0) + (off ^ ((off >> 3) & 0x70));
        asm volatile("cp.async.cg.shared.global [%0], [%1], 16;"
                     :: "r"(dst), "l"(src) : "memory");
    }
}

// ---------------------------------------------------------------------------
// GEMM: C[m,n] = sum_k Wh[m,k] * Xh[n,k]
// f16-accumulate windows (K=128) promoted into persistent fp32 accumulators.
// ---------------------------------------------------------------------------
__global__ void __launch_bounds__(GTHREADS, 1)
gemm_hmma(float* __restrict__ out) {
    extern __shared__ __align__(1024) char smem[];
    const uint32_t sb = smem_u32(smem);
    const int tid = threadIdx.x;
    const int lane = tid & 31;
    const int wid = tid >> 5;
    const int wm = wid >> 2;          // 0..1
    const int wn = wid & 3;           // 0..3

    const int mBase = blockIdx.x * BM;
    const int nBase = blockIdx.y * BN;

    const int aRow = wm * 64 + (lane & 15);
    const uint32_t aOff0 = (uint32_t)aRow * 128 + ((lane >> 4) << 4);
    const uint32_t aMask = ((((uint32_t)aRow * 128) >> 3) & 0x70);
    const int bRow = wn * 64 + (lane & 7) + ((lane >> 4) << 3);
    const uint32_t bOff0 = (uint32_t)bRow * 128 + (((lane >> 3) & 1) << 4);
    const uint32_t bMask = ((((uint32_t)bRow * 128) >> 3) & 0x70);

    float    facc[4][8][4];           // persistent fp32
    uint32_t hacc[4][8][2];           // f16 window accumulators (f16x2 pairs)
#pragma unroll
    for (int i = 0; i < 4; i++)
#pragma unroll
        for (int j = 0; j < 8; j++) {
#pragma unroll
            for (int r = 0; r < 4; r++) facc[i][j][r] = 0.0f;
            hacc[i][j][0] = 0u; hacc[i][j][1] = 0u;
        }

    produce(sb + 0 * STAGE_BYTES, tid, 0, mBase, nBase);
    asm volatile("cp.async.commit_group;" ::: "memory");
    produce(sb + 1 * STAGE_BYTES, tid, 1, mBase, nBase);
    asm volatile("cp.async.commit_group;" ::: "memory");
    produce(sb + 2 * STAGE_BYTES, tid, 2, mBase, nBase);
    asm volatile("cp.async.commit_group;" ::: "memory");

    for (int i = 0; i < KITERS; i++) {
        asm volatile("cp.async.wait_group 2;" ::: "memory");
        __syncthreads();

        if (i + 3 < KITERS)
            produce(sb + ((i + 3) % NST) * STAGE_BYTES, tid, i + 3, mBase, nBase);
        asm volatile("cp.async.commit_group;" ::: "memory");

        const uint32_t stA = sb + (i % NST) * STAGE_BYTES;
        const uint32_t stB = stA + A_BYTES;

#pragma unroll
        for (int kk = 0; kk < 4; kk++) {
            uint32_t a[4][4], b[4][4];
#pragma unroll
            for (int mt = 0; mt < 4; mt++) {
                uint32_t off = aOff0 + (uint32_t)mt * 16 * 128 + kk * 32;
                ldsm_x4(a[mt][0], a[mt][1], a[mt][2], a[mt][3],
                        stA + (off ^ aMask));
            }
#pragma unroll
            for (int nt = 0; nt < 4; nt++) {
                uint32_t off = bOff0 + (uint32_t)nt * 16 * 128 + kk * 32;
                ldsm_x4(b[nt][0], b[nt][1], b[nt][2], b[nt][3],
                        stB + (off ^ bMask));
            }
#pragma unroll
            for (int mt = 0; mt < 4; mt++)
#pragma unroll
                for (int nt = 0; nt < 4; nt++) {
                    mma16816h(hacc[mt][2 * nt][0],     hacc[mt][2 * nt][1],
                              a[mt], b[nt][0], b[nt][1]);
                    mma16816h(hacc[mt][2 * nt + 1][0], hacc[mt][2 * nt + 1][1],
                              a[mt], b[nt][2], b[nt][3]);
                }
        }

        // Promote every 2 iterations (K-window = 128)
        if ((i & 1) == 1) {
#pragma unroll
            for (int mt = 0; mt < 4; mt++)
#pragma unroll
                for (int j = 0; j < 8; j++) {
                    float2 f0 = __half22float2(
                        *reinterpret_cast<__half2*>(&hacc[mt][j][0]));
                    float2 f1 = __half22float2(
                        *reinterpret_cast<__half2*>(&hacc[mt][j][1]));
                    facc[mt][j][0] += f0.x;
                    facc[mt][j][1] += f0.y;
                    facc[mt][j][2] += f1.x;
                    facc[mt][j][3] += f1.y;
                    hacc[mt][j][0] = 0u;
                    hacc[mt][j][1] = 0u;
                }
        }
    }

    // Epilogue: direct stores; each 4-lane group writes a full 32B sector.
    const int b2 = nBase / SEQ;
    const int s0 = nBase % SEQ;
    const int mW = mBase + wm * 64;
    const int nW = s0 + wn * 64;
    const int rl = lane >> 2;
    const int cl = (lane & 3) * 2;
#pragma unroll
    for (int mt = 0; mt < 4; mt++) {
#pragma unroll
        for (int j = 0; j < 8; j++) {
            size_t base = ((size_t)b2 * MDIM + mW + mt * 16 + rl) * SEQ + nW + j * 8 + cl;
            *reinterpret_cast<float2*>(&out[base]) =
                make_float2(facc[mt][j][0], facc[mt][j][1]);
            *reinterpret_cast<float2*>(&out[base + 8 * SEQ]) =
                make_float2(facc[mt][j][2], facc[mt][j][3]);
        }
    }
}

// ---------------------------------------------------------------------------
// Launch
// ---------------------------------------------------------------------------
extern "C" void kernel_launch(void* const* d_in, const int* in_sizes, int n_in,
                              void* d_out, int out_size) {
    const float* x    = (const float*)d_in[0];   // [B, S, K]
    const float* w    = (const float*)d_in[1];   // [M, K]
    const int*   mask = (const int*)d_in[2];     // [M, K] bool -> int32
    float* out = (float*)d_out;                  // [B, M, S]

    convert_w_kernel<<<2048, 256>>>(w, mask);
    convert_x_kernel<<<8192, 256>>>(x);

    cudaFuncSetAttribute(gemm_hmma,
                         cudaFuncAttributeMaxDynamicSharedMemorySize, SMEM_TOTAL);
    dim3 grid(MDIM / BM, NDIM / BN);   // (32, 64): m fastest -> W stays in L2
    gemm_hmma<<<grid, GTHREADS, SMEM_TOTAL>>>(out);
}

// round 10
// speedup vs baseline: 1.0619x; 1.0619x over previous
#include <cuda_runtime.h>
#include <cuda_fp16.h>
#include <cstdint>

// Problem dims
#define BATCH 8
#define SEQ   2048
#define KDIM  4096
#define MDIM  4096
#define NDIM  (BATCH * SEQ)   // 16384

// GEMM tiling: CTA 128x256x64, 16 warps (4m x 4n), warp tile 32x64
#define BM 128
#define BN 256
#define BK 64
#define NST 4
#define GTHREADS 512
#define KITERS (KDIM / BK)    // 64

#define A_BYTES (BM * 128)                 // 16384
#define B_BYTES (BN * 128)                 // 32768
#define STAGE_BYTES (A_BYTES + B_BYTES)    // 49152
#define SMEM_TOTAL (NST * STAGE_BYTES)     // 196608

// fp16 scratch
__device__ __align__(16) __half g_Wh[(size_t)MDIM * KDIM];   // 32 MB
__device__ __align__(16) __half g_Xh[(size_t)NDIM * KDIM];   // 128 MB

// ---------------------------------------------------------------------------
// Fused conversion kernel: blocks [0, 2048) -> W*mask, [2048, 10240) -> X
// ---------------------------------------------------------------------------
__global__ void convert_all(const float* __restrict__ x,
                            const float* __restrict__ w,
                            const int* __restrict__ mask) {
    if (blockIdx.x < 2048) {
        size_t total4 = (size_t)MDIM * KDIM / 4;
        for (size_t i = (size_t)blockIdx.x * blockDim.x + threadIdx.x;
             i < total4; i += (size_t)2048 * blockDim.x) {
            float4 wv = reinterpret_cast<const float4*>(w)[i];
            int4   mv = reinterpret_cast<const int4*>(mask)[i];
            float a = mv.x ? wv.x : 0.0f;
            float b = mv.y ? wv.y : 0.0f;
            float c = mv.z ? wv.z : 0.0f;
            float d = mv.w ? wv.w : 0.0f;
            __half2* o = reinterpret_cast<__half2*>(&g_Wh[i * 4]);
            o[0] = __floats2half2_rn(a, b);
            o[1] = __floats2half2_rn(c, d);
        }
    } else {
        size_t total4 = (size_t)NDIM * KDIM / 4;
        for (size_t i = (size_t)(blockIdx.x - 2048) * blockDim.x + threadIdx.x;
             i < total4; i += (size_t)8192 * blockDim.x) {
            float4 xv = reinterpret_cast<const float4*>(x)[i];
            __half2* o = reinterpret_cast<__half2*>(&g_Xh[i * 4]);
            o[0] = __floats2half2_rn(xv.x, xv.y);
            o[1] = __floats2half2_rn(xv.z, xv.w);
        }
    }
}

// ---------------------------------------------------------------------------
// Helpers
// ---------------------------------------------------------------------------
__device__ __forceinline__ uint32_t smem_u32(const void* p) {
    uint32_t a;
    asm("{ .reg .u64 t; cvta.to.shared.u64 t, %1; cvt.u32.u64 %0, t; }"
        : "=r"(a) : "l"(p));
    return a;
}

__device__ __forceinline__ void ldsm_x4(uint32_t& r0, uint32_t& r1,
                                        uint32_t& r2, uint32_t& r3,
                                        uint32_t addr) {
    asm volatile("ldmatrix.sync.aligned.m8n8.x4.shared.b16 {%0,%1,%2,%3}, [%4];"
                 : "=r"(r0), "=r"(r1), "=r"(r2), "=r"(r3) : "r"(addr));
}

__device__ __forceinline__ void mma16816(float* c, const uint32_t* a,
                                         uint32_t b0, uint32_t b1) {
    asm volatile(
        "mma.sync.aligned.m16n8k16.row.col.f32.f16.f16.f32 "
        "{%0,%1,%2,%3}, {%4,%5,%6,%7}, {%8,%9}, {%0,%1,%2,%3};"
        : "+f"(c[0]), "+f"(c[1]), "+f"(c[2]), "+f"(c[3])
        : "r"(a[0]), "r"(a[1]), "r"(a[2]), "r"(a[3]), "r"(b0), "r"(b1));
}

__device__ __forceinline__ void cpasync16(uint32_t dst, const void* src) {
    asm volatile("cp.async.cg.shared.global [%0], [%1], 16;"
                 :: "r"(dst), "l"(src) : "memory");
}

// ---------------------------------------------------------------------------
// GEMM: C[m,n] = sum_k Wh[m,k] * Xh[n,k]; 16 warps, 4 per SMSP.
// Producer offsets precomputed per thread; ldsm kk0 issued before produce.
// ---------------------------------------------------------------------------
__global__ void __launch_bounds__(GTHREADS, 1)
gemm_hmma(float* __restrict__ out) {
    extern __shared__ __align__(1024) char smem[];
    const uint32_t sb = smem_u32(smem);
    const int tid = threadIdx.x;
    const int lane = tid & 31;
    const int wid = tid >> 5;
    const int wm = wid >> 2;          // 0..3  (m offset wm*32)
    const int wn = wid & 3;           // 0..3  (n offset wn*64)

    const int mBase = blockIdx.x * BM;
    const int nBase = blockIdx.y * BN;

    // ---- Precomputed producer offsets (fixed per thread) ----
    // A chunks t=0,1: id = tid + t*512 in [0,1024); B chunks t=0..3: id in [0,2048)
    size_t   aG[2], bG[4];
    uint32_t aS[2], bS[4];
#pragma unroll
    for (int t = 0; t < 2; t++) {
        int id = tid + t * GTHREADS;
        int row = id >> 3, c = id & 7;
        aG[t] = (size_t)row * KDIM + c * 8;
        uint32_t off = row * 128 + c * 16;
        aS[t] = off ^ ((off >> 3) & 0x70);
    }
#pragma unroll
    for (int t = 0; t < 4; t++) {
        int id = tid + t * GTHREADS;
        int row = id >> 3, c = id & 7;
        bG[t] = (size_t)row * KDIM + c * 8;
        uint32_t off = row * 128 + c * 16;
        bS[t] = A_BYTES + (off ^ ((off >> 3) & 0x70));
    }
    const __half* aBase = &g_Wh[(size_t)mBase * KDIM];
    const __half* bBase = &g_Xh[(size_t)nBase * KDIM];

    // Per-lane ldmatrix offsets
    const int aRow = wm * 32 + (lane & 15);
    const uint32_t aOff0 = (uint32_t)aRow * 128 + ((lane >> 4) << 4);
    const uint32_t aMask = ((((uint32_t)aRow * 128) >> 3) & 0x70);
    const int bRow = wn * 64 + (lane & 7) + ((lane >> 4) << 3);
    const uint32_t bOff0 = (uint32_t)bRow * 128 + (((lane >> 3) & 1) << 4);
    const uint32_t bMask = ((((uint32_t)bRow * 128) >> 3) & 0x70);

    float acc[2][8][4];
#pragma unroll
    for (int i = 0; i < 2; i++)
#pragma unroll
        for (int j = 0; j < 8; j++)
#pragma unroll
            for (int r = 0; r < 4; r++) acc[i][j][r] = 0.0f;

    // Prefill 3 stages
#pragma unroll
    for (int s = 0; s < 3; s++) {
        uint32_t stage = sb + s * STAGE_BYTES;
        const __half* aj = aBase + s * BK;
        const __half* bj = bBase + s * BK;
#pragma unroll
        for (int t = 0; t < 2; t++) cpasync16(stage + aS[t], aj + aG[t]);
#pragma unroll
        for (int t = 0; t < 4; t++) cpasync16(stage + bS[t], bj + bG[t]);
        asm volatile("cp.async.commit_group;" ::: "memory");
    }

    for (int i = 0; i < KITERS; i++) {
        asm volatile("cp.async.wait_group 2;" ::: "memory");
        __syncthreads();

        const uint32_t stA = sb + (i % NST) * STAGE_BYTES;
        const uint32_t stB = stA + A_BYTES;

        // kk0 loads FIRST (start the smem pipeline immediately)
        uint32_t a[2][4], b[4][4];
#pragma unroll
        for (int mt = 0; mt < 2; mt++) {
            uint32_t off = aOff0 + (uint32_t)mt * 16 * 128;
            ldsm_x4(a[mt][0], a[mt][1], a[mt][2], a[mt][3], stA + (off ^ aMask));
        }
#pragma unroll
        for (int nt = 0; nt < 4; nt++) {
            uint32_t off = bOff0 + (uint32_t)nt * 16 * 128;
            ldsm_x4(b[nt][0], b[nt][1], b[nt][2], b[nt][3], stB + (off ^ bMask));
        }

        // Producer issues while kk0 ldsm is in flight
        if (i + 3 < KITERS) {
            uint32_t stage = sb + ((i + 3) % NST) * STAGE_BYTES;
            const __half* aj = aBase + (i + 3) * BK;
            const __half* bj = bBase + (i + 3) * BK;
#pragma unroll
            for (int t = 0; t < 2; t++) cpasync16(stage + aS[t], aj + aG[t]);
#pragma unroll
            for (int t = 0; t < 4; t++) cpasync16(stage + bS[t], bj + bG[t]);
        }
        asm volatile("cp.async.commit_group;" ::: "memory");

        // kk0 MMAs
#pragma unroll
        for (int mt = 0; mt < 2; mt++)
#pragma unroll
            for (int nt = 0; nt < 4; nt++) {
                mma16816(acc[mt][2 * nt],     a[mt], b[nt][0], b[nt][1]);
                mma16816(acc[mt][2 * nt + 1], a[mt], b[nt][2], b[nt][3]);
            }

        // kk = 1..3
#pragma unroll
        for (int kk = 1; kk < 4; kk++) {
#pragma unroll
            for (int mt = 0; mt < 2; mt++) {
                uint32_t off = aOff0 + (uint32_t)mt * 16 * 128 + kk * 32;
                ldsm_x4(a[mt][0], a[mt][1], a[mt][2], a[mt][3], stA + (off ^ aMask));
            }
#pragma unroll
            for (int nt = 0; nt < 4; nt++) {
                uint32_t off = bOff0 + (uint32_t)nt * 16 * 128 + kk * 32;
                ldsm_x4(b[nt][0], b[nt][1], b[nt][2], b[nt][3], stB + (off ^ bMask));
            }
#pragma unroll
            for (int mt = 0; mt < 2; mt++)
#pragma unroll
                for (int nt = 0; nt < 4; nt++) {
                    mma16816(acc[mt][2 * nt],     a[mt], b[nt][0], b[nt][1]);
                    mma16816(acc[mt][2 * nt + 1], a[mt], b[nt][2], b[nt][3]);
                }
        }
    }

    // Epilogue: direct stores; each 4-lane group writes a full 32B sector.
    const int b2 = nBase / SEQ;
    const int s0 = nBase % SEQ;
    const int mW = mBase + wm * 32;
    const int nW = s0 + wn * 64;
    const int rl = lane >> 2;
    const int cl = (lane & 3) * 2;
#pragma unroll
    for (int mt = 0; mt < 2; mt++) {
#pragma unroll
        for (int j = 0; j < 8; j++) {
            size_t base = ((size_t)b2 * MDIM + mW + mt * 16 + rl) * SEQ + nW + j * 8 + cl;
            *reinterpret_cast<float2*>(&out[base]) =
                make_float2(acc[mt][j][0], acc[mt][j][1]);
            *reinterpret_cast<float2*>(&out[base + 8 * SEQ]) =
                make_float2(acc[mt][j][2], acc[mt][j][3]);
        }
    }
}

// ---------------------------------------------------------------------------
// Launch
// ---------------------------------------------------------------------------
extern "C" void kernel_launch(void* const* d_in, const int* in_sizes, int n_in,
                              void* d_out, int out_size) {
    const float* x    = (const float*)d_in[0];   // [B, S, K]
    const float* w    = (const float*)d_in[1];   // [M, K]
    const int*   mask = (const int*)d_in[2];     // [M, K] bool -> int32
    float* out = (float*)d_out;                  // [B, M, S]

    convert_all<<<10240, 256>>>(x, w, mask);

    cudaFuncSetAttribute(gemm_hmma,
                         cudaFuncAttributeMaxDynamicSharedMemorySize, SMEM_TOTAL);
    dim3 grid(MDIM / BM, NDIM / BN);   // (32, 64): m fastest -> W stays in L2
    gemm_hmma<<<grid, GTHREADS, SMEM_TOTAL>>>(out);
}

// round 11
// speedup vs baseline: 1.2423x; 1.1699x over previous
#include <cuda_runtime.h>
#include <cuda_fp16.h>
#include <cstdint>

// Problem dims
#define BATCH 8
#define SEQ   2048
#define KDIM  4096
#define MDIM  4096
#define NDIM  (BATCH * SEQ)   // 16384

// GEMM tiling: CTA 128x128x64, 8 warps (2m x 4n), warp tile 64x32; 2 CTAs/SM
#define BM 128
#define BN 128
#define BK 64
#define NST 3
#define GTHREADS 256
#define KITERS (KDIM / BK)    // 64

#define A_BYTES (BM * 128)                 // 16384
#define B_BYTES (BN * 128)                 // 16384
#define STAGE_BYTES (A_BYTES + B_BYTES)    // 32768
#define SMEM_TOTAL (NST * STAGE_BYTES)     // 98304 -> 2 CTAs per SM

// fp16 scratch
__device__ __align__(16) __half g_Wh[(size_t)MDIM * KDIM];   // 32 MB
__device__ __align__(16) __half g_Xh[(size_t)NDIM * KDIM];   // 128 MB

// ---------------------------------------------------------------------------
// Fused conversion kernel: blocks [0, 2048) -> W*mask, [2048, 10240) -> X
// ---------------------------------------------------------------------------
__global__ void convert_all(const float* __restrict__ x,
                            const float* __restrict__ w,
                            const int* __restrict__ mask) {
    if (blockIdx.x < 2048) {
        size_t total4 = (size_t)MDIM * KDIM / 4;
        for (size_t i = (size_t)blockIdx.x * blockDim.x + threadIdx.x;
             i < total4; i += (size_t)2048 * blockDim.x) {
            float4 wv = reinterpret_cast<const float4*>(w)[i];
            int4   mv = reinterpret_cast<const int4*>(mask)[i];
            float a = mv.x ? wv.x : 0.0f;
            float b = mv.y ? wv.y : 0.0f;
            float c = mv.z ? wv.z : 0.0f;
            float d = mv.w ? wv.w : 0.0f;
            __half2* o = reinterpret_cast<__half2*>(&g_Wh[i * 4]);
            o[0] = __floats2half2_rn(a, b);
            o[1] = __floats2half2_rn(c, d);
        }
    } else {
        size_t total4 = (size_t)NDIM * KDIM / 4;
        for (size_t i = (size_t)(blockIdx.x - 2048) * blockDim.x + threadIdx.x;
             i < total4; i += (size_t)8192 * blockDim.x) {
            float4 xv = reinterpret_cast<const float4*>(x)[i];
            __half2* o = reinterpret_cast<__half2*>(&g_Xh[i * 4]);
            o[0] = __floats2half2_rn(xv.x, xv.y);
            o[1] = __floats2half2_rn(xv.z, xv.w);
        }
    }
}

// ---------------------------------------------------------------------------
// Helpers
// ---------------------------------------------------------------------------
__device__ __forceinline__ uint32_t smem_u32(const void* p) {
    uint32_t a;
    asm("{ .reg .u64 t; cvta.to.shared.u64 t, %1; cvt.u32.u64 %0, t; }"
        : "=r"(a) : "l"(p));
    return a;
}

__device__ __forceinline__ void ldsm_x4(uint32_t& r0, uint32_t& r1,
                                        uint32_t& r2, uint32_t& r3,
                                        uint32_t addr) {
    asm volatile("ldmatrix.sync.aligned.m8n8.x4.shared.b16 {%0,%1,%2,%3}, [%4];"
                 : "=r"(r0), "=r"(r1), "=r"(r2), "=r"(r3) : "r"(addr));
}

__device__ __forceinline__ void mma16816(float* c, const uint32_t* a,
                                         uint32_t b0, uint32_t b1) {
    asm volatile(
        "mma.sync.aligned.m16n8k16.row.col.f32.f16.f16.f32 "
        "{%0,%1,%2,%3}, {%4,%5,%6,%7}, {%8,%9}, {%0,%1,%2,%3};"
        : "+f"(c[0]), "+f"(c[1]), "+f"(c[2]), "+f"(c[3])
        : "r"(a[0]), "r"(a[1]), "r"(a[2]), "r"(a[3]), "r"(b0), "r"(b1));
}

// ---------------------------------------------------------------------------
// Producer: 2048 x 16B cp.async per stage (A 1024, B 1024), 8 per thread.
// ---------------------------------------------------------------------------
__device__ __forceinline__ void produce(uint32_t stage, int tid, int j,
                                        int mBase, int nBase) {
    const __half* aseg = &g_Wh[(size_t)mBase * KDIM + j * BK];
    const __half* bseg = &g_Xh[(size_t)nBase * KDIM + j * BK];
#pragma unroll
    for (int t = 0; t < 8; t++) {
        int id = tid + t * GTHREADS;          // 0..2047
        int isB = (id >= 1024);
        int lid = id & 1023;
        int row = lid >> 3;
        int c   = lid & 7;
        const __half* src = (isB ? bseg : aseg) + (size_t)row * KDIM + c * 8;
        uint32_t off = row * 128 + c * 16;
        uint32_t dst = stage + (isB ? A_BYTES : 0) + (off ^ ((off >> 3) & 0x70));
        asm volatile("cp.async.cg.shared.global [%0], [%1], 16;"
                     :: "r"(dst), "l"(src) : "memory");
    }
}

// ---------------------------------------------------------------------------
// GEMM: C[m,n] = sum_k Wh[m,k] * Xh[n,k]; 2 CTAs per SM hide barrier bubbles
// ---------------------------------------------------------------------------
__global__ void __launch_bounds__(GTHREADS, 2)
gemm_hmma(float* __restrict__ out) {
    extern __shared__ __align__(1024) char smem[];
    const uint32_t sb = smem_u32(smem);
    const int tid = threadIdx.x;
    const int lane = tid & 31;
    const int wid = tid >> 5;
    const int wm = wid >> 2;          // 0..1  (m offset wm*64)
    const int wn = wid & 3;           // 0..3  (n offset wn*32)

    const int mBase = blockIdx.x * BM;
    const int nBase = blockIdx.y * BN;

    // Per-lane ldmatrix offsets
    const int aRow = wm * 64 + (lane & 15);
    const uint32_t aOff0 = (uint32_t)aRow * 128 + ((lane >> 4) << 4);
    const uint32_t aMask = ((((uint32_t)aRow * 128) >> 3) & 0x70);
    const int bRow = wn * 32 + (lane & 7) + ((lane >> 4) << 3);
    const uint32_t bOff0 = (uint32_t)bRow * 128 + (((lane >> 3) & 1) << 4);
    const uint32_t bMask = ((((uint32_t)bRow * 128) >> 3) & 0x70);

    float acc[4][4][4];               // 4 m16 x 4 n8, 64 regs
#pragma unroll
    for (int i = 0; i < 4; i++)
#pragma unroll
        for (int j = 0; j < 4; j++)
#pragma unroll
            for (int r = 0; r < 4; r++) acc[i][j][r] = 0.0f;

    produce(sb + 0 * STAGE_BYTES, tid, 0, mBase, nBase);
    asm volatile("cp.async.commit_group;" ::: "memory");
    produce(sb + 1 * STAGE_BYTES, tid, 1, mBase, nBase);
    asm volatile("cp.async.commit_group;" ::: "memory");

    for (int i = 0; i < KITERS; i++) {
        asm volatile("cp.async.wait_group 1;" ::: "memory");
        __syncthreads();

        if (i + 2 < KITERS)
            produce(sb + ((i + 2) % NST) * STAGE_BYTES, tid, i + 2, mBase, nBase);
        asm volatile("cp.async.commit_group;" ::: "memory");

        const uint32_t stA = sb + (i % NST) * STAGE_BYTES;
        const uint32_t stB = stA + A_BYTES;

#pragma unroll
        for (int kk = 0; kk < 4; kk++) {
            uint32_t a[4][4], b[2][4];
#pragma unroll
            for (int mt = 0; mt < 4; mt++) {
                uint32_t off = aOff0 + (uint32_t)mt * 16 * 128 + kk * 32;
                ldsm_x4(a[mt][0], a[mt][1], a[mt][2], a[mt][3],
                        stA + (off ^ aMask));
            }
#pragma unroll
            for (int nt = 0; nt < 2; nt++) {
                uint32_t off = bOff0 + (uint32_t)nt * 16 * 128 + kk * 32;
                ldsm_x4(b[nt][0], b[nt][1], b[nt][2], b[nt][3],
                        stB + (off ^ bMask));
            }
#pragma unroll
            for (int mt = 0; mt < 4; mt++)
#pragma unroll
                for (int nt = 0; nt < 2; nt++) {
                    mma16816(acc[mt][2 * nt],     a[mt], b[nt][0], b[nt][1]);
                    mma16816(acc[mt][2 * nt + 1], a[mt], b[nt][2], b[nt][3]);
                }
        }
    }

    // Epilogue: direct stores; each 4-lane group writes a full 32B sector.
    const int b2 = nBase / SEQ;
    const int s0 = nBase % SEQ;
    const int mW = mBase + wm * 64;
    const int nW = s0 + wn * 32;
    const int rl = lane >> 2;
    const int cl = (lane & 3) * 2;
#pragma unroll
    for (int mt = 0; mt < 4; mt++) {
#pragma unroll
        for (int j = 0; j < 4; j++) {
            size_t base = ((size_t)b2 * MDIM + mW + mt * 16 + rl) * SEQ + nW + j * 8 + cl;
            *reinterpret_cast<float2*>(&out[base]) =
                make_float2(acc[mt][j][0], acc[mt][j][1]);
            *reinterpret_cast<float2*>(&out[base + 8 * SEQ]) =
                make_float2(acc[mt][j][2], acc[mt][j][3]);
        }
    }
}

// ---------------------------------------------------------------------------
// Launch
// ---------------------------------------------------------------------------
extern "C" void kernel_launch(void* const* d_in, const int* in_sizes, int n_in,
                              void* d_out, int out_size) {
    const float* x    = (const float*)d_in[0];   // [B, S, K]
    const float* w    = (const float*)d_in[1];   // [M, K]
    const int*   mask = (const int*)d_in[2];     // [M, K] bool -> int32
    float* out = (float*)d_out;                  // [B, M, S]

    convert_all<<<10240, 256>>>(x, w, mask);

    cudaFuncSetAttribute(gemm_hmma,
                         cudaFuncAttributeMaxDynamicSharedMemorySize, SMEM_TOTAL);
    dim3 grid(MDIM / BM, NDIM / BN);   // (32, 128): m fastest -> W stays in L2
    gemm_hmma<<<grid, GTHREADS, SMEM_TOTAL>>>(out);
}